// round 15
// baseline (speedup 1.0000x reference)
#include <cuda_runtime.h>
#include <cuda_fp16.h>
#include <cstdint>

constexpr int B = 8, NC = 19, HC = 32, WC = 64, CF = 256;
constexpr int HF = 128, WF = 256, HID = 256;
constexpr int HW = HF * WF, NPTS = 2048, CIN1 = CF + NC;   // 275
constexpr int K1P = 320;          // CIN1 padded
constexpr int AKS = 136;          // A smem row stride ([c][p] layout, halfs)
constexpr int WKS = 72;           // layer-1 W chunk row stride (halfs)
constexpr int WK2 = 264;          // resident W row stride (halfs)

__device__ float g_unc[B * HW];
__device__ int   g_idx[B * NPTS];
__device__ __half g_W1h[256 * K1P];
__device__ __half g_W2h[256 * 256];
__device__ __half g_W3h[32 * 256];
__device__ __half g_Ah[(size_t)B * K1P * NPTS];   // [b][c][p]

// ---------------- Kernel P: pre-convert weights to fp16 ----------------
__global__ void __launch_bounds__(256) prep_weights(
    const float* __restrict__ w1, const float* __restrict__ w2,
    const float* __restrict__ w3)
{
    constexpr int T1 = 256 * K1P, T2 = 256 * 256, T3 = 32 * 256;
    for (int i = blockIdx.x * 256 + threadIdx.x; i < T1 + T2 + T3;
         i += gridDim.x * 256) {
        if (i < T1) {
            int n = i / K1P, k = i - n * K1P;
            g_W1h[i] = __float2half_rn(k < CIN1 ? w1[n * CIN1 + k] : 0.f);
        } else if (i < T1 + T2) {
            int j = i - T1;
            g_W2h[j] = __float2half_rn(w2[j]);
        } else {
            int j = i - T1 - T2;
            int n = j >> 8, k = j & 255;
            g_W3h[j] = __float2half_rn(n < NC ? w3[n * HID + k] : 0.f);
        }
    }
}

// ---------------- Kernel A: upsample + uncertainty ----------------
__global__ void __launch_bounds__(WF) upsample_unc_kernel(
    const float* __restrict__ coarse, float* __restrict__ out, float* __restrict__ unc)
{
    __shared__ float sm[NC * 128];
    int w = threadIdx.x, h = blockIdx.x & (HF - 1), b = blockIdx.x >> 7;
    float yf = (float)h * ((float)(HC - 1) / (float)(HF - 1));
    int y0 = min(max((int)floorf(yf), 0), HC - 1);
    int y1 = min(y0 + 1, HC - 1);
    float wy = yf - (float)y0;
    const float* cb = coarse + (size_t)b * NC * HC * WC;
    for (int j = w; j < NC * 128; j += WF) {
        int c = j >> 7, r = (j >> 6) & 1, x = j & 63;
        sm[j] = cb[c * (HC * WC) + (r ? y1 : y0) * WC + x];
    }
    __syncthreads();
    float xf = (float)w * ((float)(WC - 1) / (float)(WF - 1));
    int x0 = min(max((int)floorf(xf), 0), WC - 1);
    int x1 = min(x0 + 1, WC - 1);
    float wx = xf - (float)x0;
    float v[NC], vmax = -3.4e38f;
#pragma unroll
    for (int c = 0; c < NC; c++) {
        float r0 = sm[c*128 + x0] * (1.f - wy) + sm[c*128 + 64 + x0] * wy;
        float r1 = sm[c*128 + x1] * (1.f - wy) + sm[c*128 + 64 + x1] * wy;
        float val = r0 * (1.f - wx) + r1 * wx;
        v[c] = val; vmax = fmaxf(vmax, val);
        out[((size_t)(b * NC + c) * HF + h) * WF + w] = val;
    }
    float s = 0.f;
#pragma unroll
    for (int c = 0; c < NC; c++) s += __expf(v[c] - vmax);
    unc[b * HW + h * WF + w] = -1.0f / s;
}

// ---------------- Kernel B: radix select + SORTED bitmap emission ----------
__device__ __forceinline__ unsigned fkey(float f) {
    unsigned u = __float_as_uint(f);
    return (u & 0x80000000u) ? ~u : (u | 0x80000000u);
}
constexpr int KPT = HW / 1024;   // 32

__global__ void __launch_bounds__(1024) topk_kernel() {
    int b = blockIdx.x, tid = threadIdx.x, lane = tid & 31, wid = tid >> 5;
    const float* u = g_unc + b * HW;
    unsigned key[KPT];
#pragma unroll
    for (int i = 0; i < KPT; i++) key[i] = fkey(u[i * 1024 + tid]);

    __shared__ unsigned h32[32][257];
    __shared__ unsigned hist[256];
    __shared__ unsigned bm_sel[1024], bm_tie[1024], scan[1024];
    __shared__ unsigned s_prefix, s_mask;
    __shared__ int s_rem;
    if (tid == 0) { s_prefix = 0; s_mask = 0; s_rem = NPTS; }

    for (int pass = 0; pass < 4; pass++) {
        int shift = (3 - pass) * 8;
        for (int j = tid; j < 32 * 257; j += 1024) ((unsigned*)h32)[j] = 0;
        __syncthreads();
        unsigned mask = s_mask, pref = s_prefix;
#pragma unroll
        for (int i = 0; i < KPT; i++) {
            unsigned k = key[i];
            bool act = (k & mask) == pref;
            unsigned bin = act ? ((k >> shift) & 255u) : 0xFFFFFFFFu;
            unsigned same = __match_any_sync(0xFFFFFFFFu, bin);
            if (act && (unsigned)(__ffs(same) - 1) == (unsigned)lane)
                h32[wid][bin] += (unsigned)__popc(same);
        }
        __syncthreads();
        if (tid < 256) {
            unsigned s = 0;
#pragma unroll
            for (int w = 0; w < 32; w++) s += h32[w][tid];
            hist[tid] = s;
        }
        __syncthreads();
        if (tid == 0) {
            int need = s_rem; unsigned cum = 0; int sel = 0;
            for (int bin = 255; bin >= 0; bin--) {
                unsigned h = hist[bin];
                if (cum + h >= (unsigned)need) { sel = bin; s_rem = need - (int)cum; break; }
                cum += h;
            }
            s_prefix = pref | ((unsigned)sel << shift);
            s_mask = mask | (0xFFu << shift);
        }
        __syncthreads();
    }
    unsigned T = s_prefix;
    int R = s_rem;

#pragma unroll
    for (int i = 0; i < KPT; i++) {
        unsigned sb = __ballot_sync(0xFFFFFFFFu, key[i] > T);
        unsigned tb = __ballot_sync(0xFFFFFFFFu, key[i] == T);
        if (lane == 0) { bm_sel[i * 32 + wid] = sb; bm_tie[i * 32 + wid] = tb; }
    }
    __syncthreads();
    unsigned selm = bm_sel[tid], tiem = bm_tie[tid];
    unsigned cnt = (unsigned)__popc(selm) | ((unsigned)__popc(tiem) << 16);
    scan[tid] = cnt;
    __syncthreads();
    for (int off = 1; off < 1024; off <<= 1) {
        unsigned v = (tid >= off) ? scan[tid - off] : 0u;
        __syncthreads();
        scan[tid] += v;
        __syncthreads();
    }
    unsigned exc = scan[tid] - cnt;
    int selpre = (int)(exc & 0xFFFFu), tiepre = (int)(exc >> 16);

    int need = R - tiepre;
    int cntt = __popc(tiem);
    int take = need <= 0 ? 0 : (need < cntt ? need : cntt);
    for (int d = cntt - take; d > 0; d--)
        tiem ^= (0x80000000u >> __clz(tiem));
    unsigned m = selm | tiem;
    int base = selpre + (tiepre < R ? tiepre : R);
    int idxbase = tid * 32;
    while (m) {
        int bit = __ffs(m) - 1;
        m &= m - 1;
        g_idx[b * NPTS + base++] = idxbase + bit;
    }
}

// ---------------- Kernel G: scattered gather -> packed fp16 A -------------
// 1280 blocks: b = blk/160, 2 channels/block, 4 warps/channel (512 pts each)
// 16 independent scattered loads in flight per thread.
__global__ void __launch_bounds__(256) gather_kernel(
    const float* __restrict__ fine, const float* __restrict__ out)
{
    __shared__ int sidx[NPTS];
    int tid = threadIdx.x, lane = tid & 31, warp = tid >> 5;
    int b = blockIdx.x / 160, rem = blockIdx.x % 160;
    for (int j = tid; j < NPTS; j += 256) sidx[j] = g_idx[b * NPTS + j];
    __syncthreads();

    int c = rem * 2 + (warp >> 2);
    int p0 = (warp & 3) * 512 + lane;
    const float* src = (c < CF)   ? (fine + ((size_t)b * CF + c) * HW)
                     : (c < CIN1) ? (out + ((size_t)b * NC + (c - CF)) * HW)
                     : nullptr;
    size_t dst = ((size_t)b * K1P + c) * NPTS;
    float v[16];
#pragma unroll
    for (int j = 0; j < 16; j++)
        v[j] = src ? __ldg(&src[sidx[p0 + j * 32]]) : 0.f;
#pragma unroll
    for (int j = 0; j < 16; j++)
        g_Ah[dst + p0 + j * 32] = __float2half_rn(v[j]);
}

// ---------------- MLP on mma.sync + ldmatrix.trans ([c][p] A) -------------
__device__ __forceinline__ void mma16816(float* d, const uint32_t* a, const uint32_t* b) {
    asm volatile(
        "mma.sync.aligned.m16n8k16.row.col.f32.f16.f16.f32 "
        "{%0,%1,%2,%3}, {%4,%5,%6,%7}, {%8,%9}, {%0,%1,%2,%3};"
        : "+f"(d[0]), "+f"(d[1]), "+f"(d[2]), "+f"(d[3])
        : "r"(a[0]), "r"(a[1]), "r"(a[2]), "r"(a[3]), "r"(b[0]), "r"(b[1]));
}
__device__ __forceinline__ void ldsm_x4t(uint32_t* r, uint32_t a) {
    asm volatile("ldmatrix.sync.aligned.m8n8.x4.trans.shared.b16 {%0,%1,%2,%3}, [%4];"
        : "=r"(r[0]), "=r"(r[1]), "=r"(r[2]), "=r"(r[3]) : "r"(a));
}
__device__ __forceinline__ void ldsm_x2(uint32_t* r, uint32_t a) {
    asm volatile("ldmatrix.sync.aligned.m8n8.x2.shared.b16 {%0,%1}, [%2];"
        : "=r"(r[0]), "=r"(r[1]) : "r"(a));
}

// smem byte offsets
constexpr int A_SM = 0;                               // 320*136*2 = 87040
constexpr int W_SM = 87040;
constexpr int WCHUNK = 256 * WKS * 2;                 // 36864 (layer-1 dbuf unit)
constexpr int SM_TOTAL = 87040 + 256 * WK2 * 2;       // 222208

__device__ __forceinline__ void ldW256(uint4* r, const __half* __restrict__ W,
                                       int wstr, int k0, int tid)
{
#pragma unroll
    for (int j = 0; j < 4; j++) {
        int idx = tid + j * 512;
        int row = idx >> 3, q = idx & 7;
        r[j] = *(const uint4*)(W + row * wstr + k0 + q * 8);
    }
}
__device__ __forceinline__ void stW256(char* sm, const uint4* r, int tid, int buf)
{
    int base = W_SM + buf * WCHUNK;
#pragma unroll
    for (int j = 0; j < 4; j++) {
        int idx = tid + j * 512;
        int row = idx >> 3, q = idx & 7;
        *(uint4*)(sm + base + (row * WKS + q * 8) * 2) = r[j];
    }
}

__global__ void __launch_bounds__(512, 1) mlp_mma_kernel(
    const float* __restrict__ b1, const float* __restrict__ b2,
    const float* __restrict__ b3, float* __restrict__ out)
{
    extern __shared__ char sm[];
    int tid = threadIdx.x, wid = tid >> 5, lane = tid & 31;
    int wm = wid & 3, wn = wid >> 2;
    int b = blockIdx.x >> 4, tb = blockIdx.x & 15;
    __shared__ int sidx[128];

    uint32_t smb = (uint32_t)__cvta_generic_to_shared(sm);

    if (tid < 128) sidx[tid] = g_idx[b * NPTS + tb * 128 + tid];

    // vectorized coalesced load of packed A [c][p] into smem (same layout)
    {
        const __half* Asrc = g_Ah + (size_t)b * K1P * NPTS + tb * 128;
#pragma unroll
        for (int j = 0; j < 10; j++) {
            int idx = tid + j * 512;
            int row = idx >> 4, q = idx & 15;
            uint4 v = *(const uint4*)(Asrc + (size_t)row * NPTS + q * 8);
            *(uint4*)(sm + A_SM + (row * AKS + q * 8) * 2) = v;
        }
    }

    float acc[2][8][4];
    uint4 rwv[4];
    int qrow = lane >> 2, qk = 2 * (lane & 3);
    int lg = lane >> 3, lr = lane & 7;
    int a_k_off = (lg >> 1) * 8 + lr;
    int a_m_off = (lg & 1) * 8;
    int w_row = lane & 7;
    int w_col_off = ((lane >> 3) & 1) * 8;

#pragma unroll
    for (int t = 0; t < 2; t++)
#pragma unroll
        for (int u = 0; u < 8; u++)
#pragma unroll
            for (int q = 0; q < 4; q++) acc[t][u][q] = 0.f;

    // ================= layer 1: K64 chunks, double-buffered =================
    ldW256(rwv, g_W1h, K1P, 0, tid);
    stW256(sm, rwv, tid, 0);
    ldW256(rwv, g_W1h, K1P, 64, tid);
    __syncthreads();
    for (int s = 0; s < 5; s++) {
        int wbase = W_SM + (s & 1) * WCHUNK;
#pragma unroll
        for (int half = 0; half < 4; half++) {
            int kg = s * 64 + half * 16;
            int kl = half * 16;
            uint32_t ah[2][4];
#pragma unroll
            for (int t = 0; t < 2; t++) {
                int m0 = wm * 32 + t * 16;
                ldsm_x4t(ah[t], smb + A_SM +
                         (uint32_t)(((kg + a_k_off) * AKS + m0 + a_m_off) * 2));
            }
#pragma unroll
            for (int u = 0; u < 8; u++) {
                int n = wn * 64 + u * 8 + w_row;
                uint32_t bh[2];
                ldsm_x2(bh, smb + (uint32_t)(wbase + (n * WKS + kl + w_col_off) * 2));
#pragma unroll
                for (int t = 0; t < 2; t++)
                    mma16816(acc[t][u], ah[t], bh);
            }
        }
        if (s + 1 < 5) {
            stW256(sm, rwv, tid, (s + 1) & 1);
            if (s + 2 < 5) ldW256(rwv, g_W1h, K1P, (s + 2) * 64, tid);
        }
        __syncthreads();
    }

    // epilogue 1: bias + relu -> A [c][p] ; stage full W2 resident
#pragma unroll
    for (int t = 0; t < 2; t++) {
#pragma unroll
        for (int u = 0; u < 8; u++) {
            int r  = wm * 32 + t * 16 + qrow;
            int cc = wn * 64 + u * 8 + qk;
            float bb0 = __ldg(&b1[cc]), bb1 = __ldg(&b1[cc + 1]);
            float v0 = fmaxf(acc[t][u][0] + bb0, 0.f);
            float v1 = fmaxf(acc[t][u][1] + bb1, 0.f);
            float v2 = fmaxf(acc[t][u][2] + bb0, 0.f);
            float v3 = fmaxf(acc[t][u][3] + bb1, 0.f);
            *(__half*)(sm + A_SM + (cc * AKS + r) * 2)           = __float2half_rn(v0);
            *(__half*)(sm + A_SM + ((cc + 1) * AKS + r) * 2)     = __float2half_rn(v1);
            *(__half*)(sm + A_SM + (cc * AKS + r + 8) * 2)       = __float2half_rn(v2);
            *(__half*)(sm + A_SM + ((cc + 1) * AKS + r + 8) * 2) = __float2half_rn(v3);
            acc[t][u][0] = acc[t][u][1] = acc[t][u][2] = acc[t][u][3] = 0.f;
        }
    }
#pragma unroll
    for (int j = 0; j < 16; j++) {
        int idx = tid + j * 512;
        int row = idx >> 5, q = idx & 31;
        *(uint4*)(sm + W_SM + (row * WK2 + q * 8) * 2) =
            *(const uint4*)(g_W2h + row * 256 + q * 8);
    }
    __syncthreads();

    // ================= layer 2: barrier-free mainloop =================
#pragma unroll 4
    for (int kb = 0; kb < 16; kb++) {
        int kg = kb * 16;
        uint32_t ah[2][4];
#pragma unroll
        for (int t = 0; t < 2; t++) {
            int m0 = wm * 32 + t * 16;
            ldsm_x4t(ah[t], smb + A_SM +
                     (uint32_t)(((kg + a_k_off) * AKS + m0 + a_m_off) * 2));
        }
#pragma unroll
        for (int u = 0; u < 8; u++) {
            int n = wn * 64 + u * 8 + w_row;
            uint32_t bh[2];
            ldsm_x2(bh, smb + W_SM + (uint32_t)((n * WK2 + kg + w_col_off) * 2));
#pragma unroll
            for (int t = 0; t < 2; t++)
                mma16816(acc[t][u], ah[t], bh);
        }
    }
    __syncthreads();

    // epilogue 2 -> A ; stage W3 (32x256, stride WK2)
#pragma unroll
    for (int t = 0; t < 2; t++) {
#pragma unroll
        for (int u = 0; u < 8; u++) {
            int r  = wm * 32 + t * 16 + qrow;
            int cc = wn * 64 + u * 8 + qk;
            float bb0 = __ldg(&b2[cc]), bb1 = __ldg(&b2[cc + 1]);
            float v0 = fmaxf(acc[t][u][0] + bb0, 0.f);
            float v1 = fmaxf(acc[t][u][1] + bb1, 0.f);
            float v2 = fmaxf(acc[t][u][2] + bb0, 0.f);
            float v3 = fmaxf(acc[t][u][3] + bb1, 0.f);
            *(__half*)(sm + A_SM + (cc * AKS + r) * 2)           = __float2half_rn(v0);
            *(__half*)(sm + A_SM + ((cc + 1) * AKS + r) * 2)     = __float2half_rn(v1);
            *(__half*)(sm + A_SM + (cc * AKS + r + 8) * 2)       = __float2half_rn(v2);
            *(__half*)(sm + A_SM + ((cc + 1) * AKS + r + 8) * 2) = __float2half_rn(v3);
            acc[t][u][0] = acc[t][u][1] = acc[t][u][2] = acc[t][u][3] = 0.f;
        }
    }
#pragma unroll
    for (int j = 0; j < 2; j++) {
        int idx = tid + j * 512;
        int row = idx >> 5, q = idx & 31;
        *(uint4*)(sm + W_SM + (row * WK2 + q * 8) * 2) =
            *(const uint4*)(g_W3h + row * 256 + q * 8);
    }
    __syncthreads();

    // ================= layer 3 (N=19 padded 32, wn==0 computes) ============
    if (wn == 0) {
#pragma unroll 4
        for (int kb = 0; kb < 16; kb++) {
            int kg = kb * 16;
            uint32_t ah[2][4];
#pragma unroll
            for (int t = 0; t < 2; t++) {
                int m0 = wm * 32 + t * 16;
                ldsm_x4t(ah[t], smb + A_SM +
                         (uint32_t)(((kg + a_k_off) * AKS + m0 + a_m_off) * 2));
            }
#pragma unroll
            for (int u = 0; u < 4; u++) {
                int n = u * 8 + w_row;
                uint32_t bh[2];
                ldsm_x2(bh, smb + W_SM + (uint32_t)((n * WK2 + kg + w_col_off) * 2));
#pragma unroll
                for (int t = 0; t < 2; t++)
                    mma16816(acc[t][u], ah[t], bh);
            }
        }

        // scatter point logits
#pragma unroll
        for (int t = 0; t < 2; t++) {
#pragma unroll
            for (int u = 0; u < 4; u++) {
                int cc = u * 8 + qk;
#pragma unroll
                for (int half = 0; half < 2; half++) {
                    int r = wm * 32 + t * 16 + qrow + half * 8;
                    int pix = sidx[r];
                    float v0 = acc[t][u][half * 2 + 0];
                    float v1 = acc[t][u][half * 2 + 1];
                    if (cc < NC)
                        out[((size_t)b * NC + cc) * HW + pix] = v0 + __ldg(&b3[cc]);
                    if (cc + 1 < NC)
                        out[((size_t)b * NC + cc + 1) * HW + pix] = v1 + __ldg(&b3[cc + 1]);
                }
            }
        }
    }
}

// ---------------- launch (single stream; no stream/event objects) ----------
extern "C" void kernel_launch(void* const* d_in, const int* in_sizes, int n_in,
                              void* d_out, int out_size)
{
    (void)in_sizes; (void)n_in; (void)out_size;
    const float* coarse = (const float*)d_in[0];
    const float* fine   = (const float*)d_in[1];
    const float* w1 = (const float*)d_in[2];
    const float* b1 = (const float*)d_in[3];
    const float* w2 = (const float*)d_in[4];
    const float* b2 = (const float*)d_in[5];
    const float* w3 = (const float*)d_in[6];
    const float* b3 = (const float*)d_in[7];
    float* out = (float*)d_out;

    static float* unc = nullptr;
    static bool init_done = false;
    if (!init_done) {
        cudaGetSymbolAddress((void**)&unc, g_unc);
        cudaFuncSetAttribute(mlp_mma_kernel,
                             cudaFuncAttributeMaxDynamicSharedMemorySize, SM_TOTAL);
        init_done = true;
    }

    prep_weights<<<152, 256>>>(w1, w2, w3);
    upsample_unc_kernel<<<B * HF, WF>>>(coarse, out, unc);
    topk_kernel<<<B, 1024>>>();
    gather_kernel<<<B * 160, 256>>>(fine, out);
    mlp_mma_kernel<<<B * 16, 512, SM_TOTAL>>>(b1, b2, b3, out);
}

// round 16
// speedup vs baseline: 1.0534x; 1.0534x over previous
#include <cuda_runtime.h>
#include <cuda_fp16.h>
#include <cstdint>

constexpr int B = 8, NC = 19, HC = 32, WC = 64, CF = 256;
constexpr int HF = 128, WF = 256, HID = 256;
constexpr int HW = HF * WF, NPTS = 2048, CIN1 = CF + NC;   // 275
constexpr int K1P = 288;          // CIN1 padded to 18x16
constexpr int AKS = 136;          // A smem row stride ([c][p] layout, halfs)
constexpr int WKS = 72;           // layer-1 W chunk row stride (halfs)
constexpr int WK2 = 264;          // resident W row stride (halfs)

__device__ float g_unc[B * HW];
__device__ int   g_idx[B * NPTS];
__device__ __half g_W1h[256 * K1P];
__device__ __half g_W2h[256 * 256];
__device__ __half g_W3h[32 * 256];
__device__ __half g_Ah[(size_t)B * K1P * NPTS];   // [b][c][p]

// ---------------- Kernel A: upsample + uncertainty (+ inline weight prep) --
__global__ void __launch_bounds__(WF) upsample_unc_kernel(
    const float* __restrict__ coarse, float* __restrict__ out,
    float* __restrict__ unc,
    const float* __restrict__ w1, const float* __restrict__ w2,
    const float* __restrict__ w3)
{
    // --- folded weight prep: one element per thread (grid = 1024x256) ---
    {
        constexpr int T1 = 256 * K1P, T2 = 256 * 256, T3 = 32 * 256;
        int i = blockIdx.x * WF + threadIdx.x;
        if (i < T1) {
            int n = i / K1P, k = i - n * K1P;
            g_W1h[i] = __float2half_rn(k < CIN1 ? w1[n * CIN1 + k] : 0.f);
        } else if (i < T1 + T2) {
            int j = i - T1;
            g_W2h[j] = __float2half_rn(w2[j]);
        } else if (i < T1 + T2 + T3) {
            int j = i - T1 - T2;
            int n = j >> 8, k = j & 255;
            g_W3h[j] = __float2half_rn(n < NC ? w3[n * HID + k] : 0.f);
        }
    }

    __shared__ float sm[NC * 128];
    int w = threadIdx.x, h = blockIdx.x & (HF - 1), b = blockIdx.x >> 7;
    float yf = (float)h * ((float)(HC - 1) / (float)(HF - 1));
    int y0 = min(max((int)floorf(yf), 0), HC - 1);
    int y1 = min(y0 + 1, HC - 1);
    float wy = yf - (float)y0;
    const float* cb = coarse + (size_t)b * NC * HC * WC;
    for (int j = w; j < NC * 128; j += WF) {
        int c = j >> 7, r = (j >> 6) & 1, x = j & 63;
        sm[j] = cb[c * (HC * WC) + (r ? y1 : y0) * WC + x];
    }
    __syncthreads();
    float xf = (float)w * ((float)(WC - 1) / (float)(WF - 1));
    int x0 = min(max((int)floorf(xf), 0), WC - 1);
    int x1 = min(x0 + 1, WC - 1);
    float wx = xf - (float)x0;
    float v[NC], vmax = -3.4e38f;
#pragma unroll
    for (int c = 0; c < NC; c++) {
        float r0 = sm[c*128 + x0] * (1.f - wy) + sm[c*128 + 64 + x0] * wy;
        float r1 = sm[c*128 + x1] * (1.f - wy) + sm[c*128 + 64 + x1] * wy;
        float val = r0 * (1.f - wx) + r1 * wx;
        v[c] = val; vmax = fmaxf(vmax, val);
        out[((size_t)(b * NC + c) * HF + h) * WF + w] = val;
    }
    float s = 0.f;
#pragma unroll
    for (int c = 0; c < NC; c++) s += __expf(v[c] - vmax);
    unc[b * HW + h * WF + w] = -1.0f / s;
}

// ---------------- Kernel B: radix select + SORTED bitmap emission ----------
__device__ __forceinline__ unsigned fkey(float f) {
    unsigned u = __float_as_uint(f);
    return (u & 0x80000000u) ? ~u : (u | 0x80000000u);
}
constexpr int KPT = HW / 1024;   // 32

__global__ void __launch_bounds__(1024) topk_kernel() {
    int b = blockIdx.x, tid = threadIdx.x, lane = tid & 31, wid = tid >> 5;
    const float* u = g_unc + b * HW;
    unsigned key[KPT];
#pragma unroll
    for (int i = 0; i < KPT; i++) key[i] = fkey(u[i * 1024 + tid]);

    __shared__ unsigned h32[32][257];
    __shared__ unsigned hist[256];
    __shared__ unsigned bm_sel[1024], bm_tie[1024], scan[1024];
    __shared__ unsigned s_prefix, s_mask;
    __shared__ int s_rem;
    if (tid == 0) { s_prefix = 0; s_mask = 0; s_rem = NPTS; }

    for (int pass = 0; pass < 4; pass++) {
        int shift = (3 - pass) * 8;
        for (int j = tid; j < 32 * 257; j += 1024) ((unsigned*)h32)[j] = 0;
        __syncthreads();
        unsigned mask = s_mask, pref = s_prefix;
#pragma unroll
        for (int i = 0; i < KPT; i++) {
            unsigned k = key[i];
            bool act = (k & mask) == pref;
            unsigned bin = act ? ((k >> shift) & 255u) : 0xFFFFFFFFu;
            unsigned same = __match_any_sync(0xFFFFFFFFu, bin);
            if (act && (unsigned)(__ffs(same) - 1) == (unsigned)lane)
                h32[wid][bin] += (unsigned)__popc(same);
        }
        __syncthreads();
        if (tid < 256) {
            unsigned s = 0;
#pragma unroll
            for (int w = 0; w < 32; w++) s += h32[w][tid];
            hist[tid] = s;
        }
        __syncthreads();
        if (tid == 0) {
            int need = s_rem; unsigned cum = 0; int sel = 0;
            for (int bin = 255; bin >= 0; bin--) {
                unsigned h = hist[bin];
                if (cum + h >= (unsigned)need) { sel = bin; s_rem = need - (int)cum; break; }
                cum += h;
            }
            s_prefix = pref | ((unsigned)sel << shift);
            s_mask = mask | (0xFFu << shift);
        }
        __syncthreads();
    }
    unsigned T = s_prefix;
    int R = s_rem;

#pragma unroll
    for (int i = 0; i < KPT; i++) {
        unsigned sb = __ballot_sync(0xFFFFFFFFu, key[i] > T);
        unsigned tb = __ballot_sync(0xFFFFFFFFu, key[i] == T);
        if (lane == 0) { bm_sel[i * 32 + wid] = sb; bm_tie[i * 32 + wid] = tb; }
    }
    __syncthreads();
    unsigned selm = bm_sel[tid], tiem = bm_tie[tid];
    unsigned cnt = (unsigned)__popc(selm) | ((unsigned)__popc(tiem) << 16);
    scan[tid] = cnt;
    __syncthreads();
    for (int off = 1; off < 1024; off <<= 1) {
        unsigned v = (tid >= off) ? scan[tid - off] : 0u;
        __syncthreads();
        scan[tid] += v;
        __syncthreads();
    }
    unsigned exc = scan[tid] - cnt;
    int selpre = (int)(exc & 0xFFFFu), tiepre = (int)(exc >> 16);

    int need = R - tiepre;
    int cntt = __popc(tiem);
    int take = need <= 0 ? 0 : (need < cntt ? need : cntt);
    for (int d = cntt - take; d > 0; d--)
        tiem ^= (0x80000000u >> __clz(tiem));
    unsigned m = selm | tiem;
    int base = selpre + (tiepre < R ? tiepre : R);
    int idxbase = tid * 32;
    while (m) {
        int bit = __ffs(m) - 1;
        m &= m - 1;
        g_idx[b * NPTS + base++] = idxbase + bit;
    }
}

// ---------------- Kernel G: scattered gather -> packed fp16 A -------------
// 1152 blocks: b = blk/144, 2 channels/block, 4 warps/channel (512 pts each)
__global__ void __launch_bounds__(256) gather_kernel(
    const float* __restrict__ fine, const float* __restrict__ out)
{
    __shared__ int sidx[NPTS];
    int tid = threadIdx.x, lane = tid & 31, warp = tid >> 5;
    int b = blockIdx.x / 144, rem = blockIdx.x % 144;
    for (int j = tid; j < NPTS; j += 256) sidx[j] = g_idx[b * NPTS + j];
    __syncthreads();

    int c = rem * 2 + (warp >> 2);
    int p0 = (warp & 3) * 512 + lane;
    const float* src = (c < CF)   ? (fine + ((size_t)b * CF + c) * HW)
                     : (c < CIN1) ? (out + ((size_t)b * NC + (c - CF)) * HW)
                     : nullptr;
    size_t dst = ((size_t)b * K1P + c) * NPTS;
    float v[16];
#pragma unroll
    for (int j = 0; j < 16; j++)
        v[j] = src ? __ldg(&src[sidx[p0 + j * 32]]) : 0.f;
#pragma unroll
    for (int j = 0; j < 16; j++)
        g_Ah[dst + p0 + j * 32] = __float2half_rn(v[j]);
}

// ---------------- MLP on mma.sync + ldmatrix.trans ([c][p] A) -------------
__device__ __forceinline__ void mma16816(float* d, const uint32_t* a, const uint32_t* b) {
    asm volatile(
        "mma.sync.aligned.m16n8k16.row.col.f32.f16.f16.f32 "
        "{%0,%1,%2,%3}, {%4,%5,%6,%7}, {%8,%9}, {%0,%1,%2,%3};"
        : "+f"(d[0]), "+f"(d[1]), "+f"(d[2]), "+f"(d[3])
        : "r"(a[0]), "r"(a[1]), "r"(a[2]), "r"(a[3]), "r"(b[0]), "r"(b[1]));
}
__device__ __forceinline__ void ldsm_x4t(uint32_t* r, uint32_t a) {
    asm volatile("ldmatrix.sync.aligned.m8n8.x4.trans.shared.b16 {%0,%1,%2,%3}, [%4];"
        : "=r"(r[0]), "=r"(r[1]), "=r"(r[2]), "=r"(r[3]) : "r"(a));
}
__device__ __forceinline__ void ldsm_x2(uint32_t* r, uint32_t a) {
    asm volatile("ldmatrix.sync.aligned.m8n8.x2.shared.b16 {%0,%1}, [%2];"
        : "=r"(r[0]), "=r"(r[1]) : "r"(a));
}

// smem byte offsets
constexpr int A_SM = 0;                               // 288*136*2 = 78336
constexpr int W_SM = 78336;
constexpr int WCHUNK = 256 * WKS * 2;                 // 36864 (layer-1 dbuf unit)
constexpr int SM_TOTAL = 78336 + 256 * WK2 * 2;       // 78336 + 135168 = 213504

__device__ __forceinline__ void ldW256(uint4* r, const __half* __restrict__ W,
                                       int k0, int tid)
{
#pragma unroll
    for (int j = 0; j < 4; j++) {
        int idx = tid + j * 512;
        int row = idx >> 3, q = idx & 7;
        r[j] = *(const uint4*)(W + row * K1P + k0 + q * 8);
    }
}
__device__ __forceinline__ void stW256(char* sm, const uint4* r, int tid, int buf)
{
    int base = W_SM + buf * WCHUNK;
#pragma unroll
    for (int j = 0; j < 4; j++) {
        int idx = tid + j * 512;
        int row = idx >> 3, q = idx & 7;
        *(uint4*)(sm + base + (row * WKS + q * 8) * 2) = r[j];
    }
}
// tail chunk: 256 rows x 32 cols (k0 = 256)
__device__ __forceinline__ void ldWtail(uint4* r, const __half* __restrict__ W, int tid)
{
#pragma unroll
    for (int j = 0; j < 2; j++) {
        int idx = tid + j * 512;
        int row = idx >> 2, q = idx & 3;
        r[j] = *(const uint4*)(W + row * K1P + 256 + q * 8);
    }
}
__device__ __forceinline__ void stWtail(char* sm, const uint4* r, int tid, int buf)
{
    int base = W_SM + buf * WCHUNK;
#pragma unroll
    for (int j = 0; j < 2; j++) {
        int idx = tid + j * 512;
        int row = idx >> 2, q = idx & 3;
        *(uint4*)(sm + base + (row * WKS + q * 8) * 2) = r[j];
    }
}

__global__ void __launch_bounds__(512, 1) mlp_mma_kernel(
    const float* __restrict__ b1, const float* __restrict__ b2,
    const float* __restrict__ b3, float* __restrict__ out)
{
    extern __shared__ char sm[];
    int tid = threadIdx.x, wid = tid >> 5, lane = tid & 31;
    int wm = wid & 3, wn = wid >> 2;
    int b = blockIdx.x >> 4, tb = blockIdx.x & 15;
    __shared__ int sidx[128];

    uint32_t smb = (uint32_t)__cvta_generic_to_shared(sm);

    if (tid < 128) sidx[tid] = g_idx[b * NPTS + tb * 128 + tid];

    // vectorized coalesced load of packed A [c][p] into smem (same layout)
    {
        const __half* Asrc = g_Ah + (size_t)b * K1P * NPTS + tb * 128;
#pragma unroll
        for (int j = 0; j < 9; j++) {           // 288 rows * 16 uint4 = 4608
            int idx = tid + j * 512;
            int row = idx >> 4, q = idx & 15;
            uint4 v = *(const uint4*)(Asrc + (size_t)row * NPTS + q * 8);
            *(uint4*)(sm + A_SM + (row * AKS + q * 8) * 2) = v;
        }
    }

    float acc[2][8][4];
    uint4 rwv[4];
    int qrow = lane >> 2, qk = 2 * (lane & 3);
    int lg = lane >> 3, lr = lane & 7;
    int a_k_off = (lg >> 1) * 8 + lr;
    int a_m_off = (lg & 1) * 8;
    int w_row = lane & 7;
    int w_col_off = ((lane >> 3) & 1) * 8;

#pragma unroll
    for (int t = 0; t < 2; t++)
#pragma unroll
        for (int u = 0; u < 8; u++)
#pragma unroll
            for (int q = 0; q < 4; q++) acc[t][u][q] = 0.f;

    // ===== layer 1: 4 K64 chunks + 1 K32 tail, double-buffered =====
    ldW256(rwv, g_W1h, 0, tid);
    stW256(sm, rwv, tid, 0);
    ldW256(rwv, g_W1h, 64, tid);
    __syncthreads();
    for (int s = 0; s < 5; s++) {
        int wbase = W_SM + (s & 1) * WCHUNK;
        int nhalf = (s == 4) ? 2 : 4;
        for (int half = 0; half < nhalf; half++) {
            int kg = s * 64 + half * 16;
            int kl = half * 16;
            uint32_t ah[2][4];
#pragma unroll
            for (int t = 0; t < 2; t++) {
                int m0 = wm * 32 + t * 16;
                ldsm_x4t(ah[t], smb + A_SM +
                         (uint32_t)(((kg + a_k_off) * AKS + m0 + a_m_off) * 2));
            }
#pragma unroll
            for (int u = 0; u < 8; u++) {
                int n = wn * 64 + u * 8 + w_row;
                uint32_t bh[2];
                ldsm_x2(bh, smb + (uint32_t)(wbase + (n * WKS + kl + w_col_off) * 2));
#pragma unroll
                for (int t = 0; t < 2; t++)
                    mma16816(acc[t][u], ah[t], bh);
            }
        }
        if (s + 1 < 5) {
            if (s + 1 == 4) stWtail(sm, rwv, tid, (s + 1) & 1);
            else            stW256(sm, rwv, tid, (s + 1) & 1);
            if (s + 2 < 5) {
                if (s + 2 == 4) ldWtail(rwv, g_W1h, tid);
                else            ldW256(rwv, g_W1h, (s + 2) * 64, tid);
            }
        }
        __syncthreads();
    }

    // epilogue 1: bias + relu -> A [c][p] ; stage full W2 resident
#pragma unroll
    for (int t = 0; t < 2; t++) {
#pragma unroll
        for (int u = 0; u < 8; u++) {
            int r  = wm * 32 + t * 16 + qrow;
            int cc = wn * 64 + u * 8 + qk;
            float bb0 = __ldg(&b1[cc]), bb1 = __ldg(&b1[cc + 1]);
            float v0 = fmaxf(acc[t][u][0] + bb0, 0.f);
            float v1 = fmaxf(acc[t][u][1] + bb1, 0.f);
            float v2 = fmaxf(acc[t][u][2] + bb0, 0.f);
            float v3 = fmaxf(acc[t][u][3] + bb1, 0.f);
            *(__half*)(sm + A_SM + (cc * AKS + r) * 2)           = __float2half_rn(v0);
            *(__half*)(sm + A_SM + ((cc + 1) * AKS + r) * 2)     = __float2half_rn(v1);
            *(__half*)(sm + A_SM + (cc * AKS + r + 8) * 2)       = __float2half_rn(v2);
            *(__half*)(sm + A_SM + ((cc + 1) * AKS + r + 8) * 2) = __float2half_rn(v3);
            acc[t][u][0] = acc[t][u][1] = acc[t][u][2] = acc[t][u][3] = 0.f;
        }
    }
#pragma unroll
    for (int j = 0; j < 16; j++) {
        int idx = tid + j * 512;
        int row = idx >> 5, q = idx & 31;
        *(uint4*)(sm + W_SM + (row * WK2 + q * 8) * 2) =
            *(const uint4*)(g_W2h + row * 256 + q * 8);
    }
    __syncthreads();

    // ===== layer 2: barrier-free mainloop =====
#pragma unroll 4
    for (int kb = 0; kb < 16; kb++) {
        int kg = kb * 16;
        uint32_t ah[2][4];
#pragma unroll
        for (int t = 0; t < 2; t++) {
            int m0 = wm * 32 + t * 16;
            ldsm_x4t(ah[t], smb + A_SM +
                     (uint32_t)(((kg + a_k_off) * AKS + m0 + a_m_off) * 2));
        }
#pragma unroll
        for (int u = 0; u < 8; u++) {
            int n = wn * 64 + u * 8 + w_row;
            uint32_t bh[2];
            ldsm_x2(bh, smb + W_SM + (uint32_t)((n * WK2 + kg + w_col_off) * 2));
#pragma unroll
            for (int t = 0; t < 2; t++)
                mma16816(acc[t][u], ah[t], bh);
        }
    }
    __syncthreads();

    // epilogue 2 -> A ; stage W3 (32x256, stride WK2)
#pragma unroll
    for (int t = 0; t < 2; t++) {
#pragma unroll
        for (int u = 0; u < 8; u++) {
            int r  = wm * 32 + t * 16 + qrow;
            int cc = wn * 64 + u * 8 + qk;
            float bb0 = __ldg(&b2[cc]), bb1 = __ldg(&b2[cc + 1]);
            float v0 = fmaxf(acc[t][u][0] + bb0, 0.f);
            float v1 = fmaxf(acc[t][u][1] + bb1, 0.f);
            float v2 = fmaxf(acc[t][u][2] + bb0, 0.f);
            float v3 = fmaxf(acc[t][u][3] + bb1, 0.f);
            *(__half*)(sm + A_SM + (cc * AKS + r) * 2)           = __float2half_rn(v0);
            *(__half*)(sm + A_SM + ((cc + 1) * AKS + r) * 2)     = __float2half_rn(v1);
            *(__half*)(sm + A_SM + (cc * AKS + r + 8) * 2)       = __float2half_rn(v2);
            *(__half*)(sm + A_SM + ((cc + 1) * AKS + r + 8) * 2) = __float2half_rn(v3);
            acc[t][u][0] = acc[t][u][1] = acc[t][u][2] = acc[t][u][3] = 0.f;
        }
    }
#pragma unroll
    for (int j = 0; j < 2; j++) {
        int idx = tid + j * 512;
        int row = idx >> 5, q = idx & 31;
        *(uint4*)(sm + W_SM + (row * WK2 + q * 8) * 2) =
            *(const uint4*)(g_W3h + row * 256 + q * 8);
    }
    __syncthreads();

    // ===== layer 3 (N=19 padded to 24, wn==0 computes) =====
    if (wn == 0) {
#pragma unroll 4
        for (int kb = 0; kb < 16; kb++) {
            int kg = kb * 16;
            uint32_t ah[2][4];
#pragma unroll
            for (int t = 0; t < 2; t++) {
                int m0 = wm * 32 + t * 16;
                ldsm_x4t(ah[t], smb + A_SM +
                         (uint32_t)(((kg + a_k_off) * AKS + m0 + a_m_off) * 2));
            }
#pragma unroll
            for (int u = 0; u < 3; u++) {
                int n = u * 8 + w_row;
                uint32_t bh[2];
                ldsm_x2(bh, smb + W_SM + (uint32_t)((n * WK2 + kg + w_col_off) * 2));
#pragma unroll
                for (int t = 0; t < 2; t++)
                    mma16816(acc[t][u], ah[t], bh);
            }
        }

        // scatter point logits
#pragma unroll
        for (int t = 0; t < 2; t++) {
#pragma unroll
            for (int u = 0; u < 3; u++) {
                int cc = u * 8 + qk;
#pragma unroll
                for (int half = 0; half < 2; half++) {
                    int r = wm * 32 + t * 16 + qrow + half * 8;
                    int pix = sidx[r];
                    float v0 = acc[t][u][half * 2 + 0];
                    float v1 = acc[t][u][half * 2 + 1];
                    if (cc < NC)
                        out[((size_t)b * NC + cc) * HW + pix] = v0 + __ldg(&b3[cc]);
                    if (cc + 1 < NC)
                        out[((size_t)b * NC + cc + 1) * HW + pix] = v1 + __ldg(&b3[cc + 1]);
                }
            }
        }
    }
}

// ---------------- launch (single stream) ----------------
extern "C" void kernel_launch(void* const* d_in, const int* in_sizes, int n_in,
                              void* d_out, int out_size)
{
    (void)in_sizes; (void)n_in; (void)out_size;
    const float* coarse = (const float*)d_in[0];
    const float* fine   = (const float*)d_in[1];
    const float* w1 = (const float*)d_in[2];
    const float* b1 = (const float*)d_in[3];
    const float* w2 = (const float*)d_in[4];
    const float* b2 = (const float*)d_in[5];
    const float* w3 = (const float*)d_in[6];
    const float* b3 = (const float*)d_in[7];
    float* out = (float*)d_out;

    static float* unc = nullptr;
    static bool init_done = false;
    if (!init_done) {
        cudaGetSymbolAddress((void**)&unc, g_unc);
        cudaFuncSetAttribute(mlp_mma_kernel,
                             cudaFuncAttributeMaxDynamicSharedMemorySize, SM_TOTAL);
        init_done = true;
    }

    upsample_unc_kernel<<<B * HF, WF>>>(coarse, out, unc, w1, w2, w3);
    topk_kernel<<<B, 1024>>>();
    gather_kernel<<<B * 144, 256>>>(fine, out);
    mlp_mma_kernel<<<B * 16, 512, SM_TOTAL>>>(b1, b2, b3, out);
}

// round 17
// speedup vs baseline: 1.2463x; 1.1831x over previous
#include <cuda_runtime.h>
#include <cuda_fp16.h>
#include <cstdint>

constexpr int B = 8, NC = 19, HC = 32, WC = 64, CF = 256;
constexpr int HF = 128, WF = 256, HID = 256;
constexpr int HW = HF * WF, NPTS = 2048, CIN1 = CF + NC;   // 275
constexpr int K1P = 288;          // CIN1 padded to 18x16
constexpr int AKS = 136;          // A smem row stride ([c][p] layout, halfs)
constexpr int WKS = 72;           // layer-1 W chunk row stride (halfs)
constexpr int WK2 = 264;          // resident W row stride (halfs)

__device__ float g_unc[B * HW];
__device__ int   g_idx[B * NPTS];
__device__ __half g_W1h[256 * K1P];
__device__ __half g_W2h[256 * 256];
__device__ __half g_W3h[32 * 256];
__device__ __half g_Ah[(size_t)B * K1P * NPTS];   // [b][c][p]

// ---------------- Kernel A: upsample + uncertainty (+ inline weight prep) --
__global__ void __launch_bounds__(WF) upsample_unc_kernel(
    const float* __restrict__ coarse, float* __restrict__ out,
    float* __restrict__ unc,
    const float* __restrict__ w1, const float* __restrict__ w2,
    const float* __restrict__ w3)
{
    {
        constexpr int T1 = 256 * K1P, T2 = 256 * 256, T3 = 32 * 256;
        int i = blockIdx.x * WF + threadIdx.x;
        if (i < T1) {
            int n = i / K1P, k = i - n * K1P;
            g_W1h[i] = __float2half_rn(k < CIN1 ? w1[n * CIN1 + k] : 0.f);
        } else if (i < T1 + T2) {
            int j = i - T1;
            g_W2h[j] = __float2half_rn(w2[j]);
        } else if (i < T1 + T2 + T3) {
            int j = i - T1 - T2;
            int n = j >> 8, k = j & 255;
            g_W3h[j] = __float2half_rn(n < NC ? w3[n * HID + k] : 0.f);
        }
    }

    __shared__ float sm[NC * 128];
    int w = threadIdx.x, h = blockIdx.x & (HF - 1), b = blockIdx.x >> 7;
    float yf = (float)h * ((float)(HC - 1) / (float)(HF - 1));
    int y0 = min(max((int)floorf(yf), 0), HC - 1);
    int y1 = min(y0 + 1, HC - 1);
    float wy = yf - (float)y0;
    const float* cb = coarse + (size_t)b * NC * HC * WC;
    for (int j = w; j < NC * 128; j += WF) {
        int c = j >> 7, r = (j >> 6) & 1, x = j & 63;
        sm[j] = cb[c * (HC * WC) + (r ? y1 : y0) * WC + x];
    }
    __syncthreads();
    float xf = (float)w * ((float)(WC - 1) / (float)(WF - 1));
    int x0 = min(max((int)floorf(xf), 0), WC - 1);
    int x1 = min(x0 + 1, WC - 1);
    float wx = xf - (float)x0;
    float v[NC], vmax = -3.4e38f;
#pragma unroll
    for (int c = 0; c < NC; c++) {
        float r0 = sm[c*128 + x0] * (1.f - wy) + sm[c*128 + 64 + x0] * wy;
        float r1 = sm[c*128 + x1] * (1.f - wy) + sm[c*128 + 64 + x1] * wy;
        float val = r0 * (1.f - wx) + r1 * wx;
        v[c] = val; vmax = fmaxf(vmax, val);
        out[((size_t)(b * NC + c) * HF + h) * WF + w] = val;
    }
    float s = 0.f;
#pragma unroll
    for (int c = 0; c < NC; c++) s += __expf(v[c] - vmax);
    unc[b * HW + h * WF + w] = -1.0f / s;
}

// ---------------- Kernel B: radix select, parallel scans throughout --------
__device__ __forceinline__ unsigned fkey(float f) {
    unsigned u = __float_as_uint(f);
    return (u & 0x80000000u) ? ~u : (u | 0x80000000u);
}
constexpr int KPT = HW / 1024;   // 32

__global__ void __launch_bounds__(1024) topk_kernel() {
    int b = blockIdx.x, tid = threadIdx.x, lane = tid & 31, wid = tid >> 5;
    const float* u = g_unc + b * HW;
    unsigned key[KPT];
#pragma unroll
    for (int i = 0; i < KPT; i++) key[i] = fkey(u[i * 1024 + tid]);

    __shared__ unsigned h32[32][257];
    __shared__ unsigned bm_sel[1024], bm_tie[1024];
    __shared__ unsigned wsum[32];
    __shared__ unsigned s_prefix, s_mask;
    __shared__ int s_rem;
    if (tid == 0) { s_prefix = 0; s_mask = 0; s_rem = NPTS; }
    __syncthreads();

    for (int pass = 0; pass < 4; pass++) {
        int shift = (3 - pass) * 8;
        for (int j = tid; j < 32 * 257; j += 1024) ((unsigned*)h32)[j] = 0;
        unsigned mask = s_mask, pref = s_prefix;
        __syncthreads();
#pragma unroll
        for (int i = 0; i < KPT; i++) {
            unsigned k = key[i];
            bool act = (k & mask) == pref;
            unsigned bin = act ? ((k >> shift) & 255u) : 0xFFFFFFFFu;
            unsigned same = __match_any_sync(0xFFFFFFFFu, bin);
            if (act && (unsigned)(__ffs(same) - 1) == (unsigned)lane)
                h32[wid][bin] += (unsigned)__popc(same);
        }
        __syncthreads();
        int need = s_rem;                       // stable since last pass-end barrier
        unsigned hv = 0, x = 0;
        if (tid < 256) {
            int bin = 255 - tid;                // descending-bin order
#pragma unroll
            for (int w = 0; w < 32; w++) hv += h32[w][bin];
            x = hv;                             // warp inclusive scan
#pragma unroll
            for (int o = 1; o < 32; o <<= 1) {
                unsigned y = __shfl_up_sync(0xFFFFFFFFu, x, o);
                if (lane >= o) x += y;
            }
            if (lane == 31) wsum[wid] = x;
        }
        __syncthreads();
        if (tid == 0) {
            unsigned run = 0;
#pragma unroll
            for (int w = 0; w < 8; w++) { unsigned t = wsum[w]; wsum[w] = run; run += t; }
        }
        __syncthreads();
        if (tid < 256) {
            unsigned sfx = x + wsum[wid];       // inclusive suffix count for this bin
            unsigned before = sfx - hv;         // count in strictly higher bins
            if ((int)sfx >= need && (int)before < need) {   // unique winner
                int bin = 255 - tid;
                s_prefix = pref | ((unsigned)bin << shift);
                s_mask = mask | (0xFFu << shift);
                s_rem = need - (int)before;
            }
        }
        __syncthreads();
    }
    unsigned T = s_prefix;
    int R = s_rem;

    // bitmaps (sorted emission)
#pragma unroll
    for (int i = 0; i < KPT; i++) {
        unsigned sb = __ballot_sync(0xFFFFFFFFu, key[i] > T);
        unsigned tb = __ballot_sync(0xFFFFFFFFu, key[i] == T);
        if (lane == 0) { bm_sel[i * 32 + wid] = sb; bm_tie[i * 32 + wid] = tb; }
    }
    __syncthreads();
    unsigned selm = bm_sel[tid], tiem = bm_tie[tid];
    unsigned cnt = (unsigned)__popc(selm) | ((unsigned)__popc(tiem) << 16);
    // warp scan + 32-word combine (replaces 20-barrier Hillis-Steele)
    unsigned x = cnt;
#pragma unroll
    for (int o = 1; o < 32; o <<= 1) {
        unsigned y = __shfl_up_sync(0xFFFFFFFFu, x, o);
        if (lane >= o) x += y;
    }
    if (lane == 31) wsum[wid] = x;
    __syncthreads();
    if (tid == 0) {
        unsigned run = 0;
#pragma unroll
        for (int w = 0; w < 32; w++) { unsigned t = wsum[w]; wsum[w] = run; run += t; }
    }
    __syncthreads();
    unsigned exc = x + wsum[wid] - cnt;
    int selpre = (int)(exc & 0xFFFFu), tiepre = (int)(exc >> 16);

    int need2 = R - tiepre;
    int cntt = __popc(tiem);
    int take = need2 <= 0 ? 0 : (need2 < cntt ? need2 : cntt);
    for (int d = cntt - take; d > 0; d--)
        tiem ^= (0x80000000u >> __clz(tiem));
    unsigned m = selm | tiem;
    int base = selpre + (tiepre < R ? tiepre : R);
    int idxbase = tid * 32;
    while (m) {
        int bit = __ffs(m) - 1;
        m &= m - 1;
        g_idx[b * NPTS + base++] = idxbase + bit;
    }
}

// ---------------- Kernel G: scattered gather -> packed fp16 A -------------
__global__ void __launch_bounds__(256) gather_kernel(
    const float* __restrict__ fine, const float* __restrict__ out)
{
    __shared__ int sidx[NPTS];
    int tid = threadIdx.x, lane = tid & 31, warp = tid >> 5;
    int b = blockIdx.x / 144, rem = blockIdx.x % 144;
    for (int j = tid; j < NPTS; j += 256) sidx[j] = g_idx[b * NPTS + j];
    __syncthreads();

    int c = rem * 2 + (warp >> 2);
    int p0 = (warp & 3) * 512 + lane;
    const float* src = (c < CF)   ? (fine + ((size_t)b * CF + c) * HW)
                     : (c < CIN1) ? (out + ((size_t)b * NC + (c - CF)) * HW)
                     : nullptr;
    size_t dst = ((size_t)b * K1P + c) * NPTS;
    float v[16];
#pragma unroll
    for (int j = 0; j < 16; j++)
        v[j] = src ? __ldg(&src[sidx[p0 + j * 32]]) : 0.f;
#pragma unroll
    for (int j = 0; j < 16; j++)
        g_Ah[dst + p0 + j * 32] = __float2half_rn(v[j]);
}

// ---------------- MLP on mma.sync + ldmatrix.trans ([c][p] A) -------------
__device__ __forceinline__ void mma16816(float* d, const uint32_t* a, const uint32_t* b) {
    asm volatile(
        "mma.sync.aligned.m16n8k16.row.col.f32.f16.f16.f32 "
        "{%0,%1,%2,%3}, {%4,%5,%6,%7}, {%8,%9}, {%0,%1,%2,%3};"
        : "+f"(d[0]), "+f"(d[1]), "+f"(d[2]), "+f"(d[3])
        : "r"(a[0]), "r"(a[1]), "r"(a[2]), "r"(a[3]), "r"(b[0]), "r"(b[1]));
}
__device__ __forceinline__ void ldsm_x4t(uint32_t* r, uint32_t a) {
    asm volatile("ldmatrix.sync.aligned.m8n8.x4.trans.shared.b16 {%0,%1,%2,%3}, [%4];"
        : "=r"(r[0]), "=r"(r[1]), "=r"(r[2]), "=r"(r[3]) : "r"(a));
}
__device__ __forceinline__ void ldsm_x2(uint32_t* r, uint32_t a) {
    asm volatile("ldmatrix.sync.aligned.m8n8.x2.shared.b16 {%0,%1}, [%2];"
        : "=r"(r[0]), "=r"(r[1]) : "r"(a));
}

// smem byte offsets
constexpr int A_SM = 0;                               // 288*136*2 = 78336
constexpr int W_SM = 78336;
constexpr int WCHUNK = 256 * WKS * 2;                 // 36864 (layer-1 dbuf unit)
constexpr int SM_TOTAL = 78336 + 256 * WK2 * 2;       // 213504

__device__ __forceinline__ void ldW256(uint4* r, const __half* __restrict__ W,
                                       int k0, int tid)
{
#pragma unroll
    for (int j = 0; j < 4; j++) {
        int idx = tid + j * 512;
        int row = idx >> 3, q = idx & 7;
        r[j] = *(const uint4*)(W + row * K1P + k0 + q * 8);
    }
}
__device__ __forceinline__ void stW256(char* sm, const uint4* r, int tid, int buf)
{
    int base = W_SM + buf * WCHUNK;
#pragma unroll
    for (int j = 0; j < 4; j++) {
        int idx = tid + j * 512;
        int row = idx >> 3, q = idx & 7;
        *(uint4*)(sm + base + (row * WKS + q * 8) * 2) = r[j];
    }
}
__device__ __forceinline__ void ldWtail(uint4* r, const __half* __restrict__ W, int tid)
{
#pragma unroll
    for (int j = 0; j < 2; j++) {
        int idx = tid + j * 512;
        int row = idx >> 2, q = idx & 3;
        r[j] = *(const uint4*)(W + row * K1P + 256 + q * 8);
    }
}
__device__ __forceinline__ void stWtail(char* sm, const uint4* r, int tid, int buf)
{
    int base = W_SM + buf * WCHUNK;
#pragma unroll
    for (int j = 0; j < 2; j++) {
        int idx = tid + j * 512;
        int row = idx >> 2, q = idx & 3;
        *(uint4*)(sm + base + (row * WKS + q * 8) * 2) = r[j];
    }
}

__global__ void __launch_bounds__(512, 1) mlp_mma_kernel(
    const float* __restrict__ b1, const float* __restrict__ b2,
    const float* __restrict__ b3, float* __restrict__ out)
{
    extern __shared__ char sm[];
    int tid = threadIdx.x, wid = tid >> 5, lane = tid & 31;
    int wm = wid & 3, wn = wid >> 2;
    int b = blockIdx.x >> 4, tb = blockIdx.x & 15;
    __shared__ int sidx[128];

    uint32_t smb = (uint32_t)__cvta_generic_to_shared(sm);

    if (tid < 128) sidx[tid] = g_idx[b * NPTS + tb * 128 + tid];

    {
        const __half* Asrc = g_Ah + (size_t)b * K1P * NPTS + tb * 128;
#pragma unroll
        for (int j = 0; j < 9; j++) {           // 288 rows * 16 uint4 = 4608
            int idx = tid + j * 512;
            int row = idx >> 4, q = idx & 15;
            uint4 v = *(const uint4*)(Asrc + (size_t)row * NPTS + q * 8);
            *(uint4*)(sm + A_SM + (row * AKS + q * 8) * 2) = v;
        }
    }

    float acc[2][8][4];
    uint4 rwv[4];
    int qrow = lane >> 2, qk = 2 * (lane & 3);
    int lg = lane >> 3, lr = lane & 7;
    int a_k_off = (lg >> 1) * 8 + lr;
    int a_m_off = (lg & 1) * 8;
    int w_row = lane & 7;
    int w_col_off = ((lane >> 3) & 1) * 8;

#pragma unroll
    for (int t = 0; t < 2; t++)
#pragma unroll
        for (int u = 0; u < 8; u++)
#pragma unroll
            for (int q = 0; q < 4; q++) acc[t][u][q] = 0.f;

    // ===== layer 1: 4 K64 chunks + 1 K32 tail, double-buffered =====
    ldW256(rwv, g_W1h, 0, tid);
    stW256(sm, rwv, tid, 0);
    ldW256(rwv, g_W1h, 64, tid);
    __syncthreads();
    for (int s = 0; s < 5; s++) {
        int wbase = W_SM + (s & 1) * WCHUNK;
        int nhalf = (s == 4) ? 2 : 4;
        for (int half = 0; half < nhalf; half++) {
            int kg = s * 64 + half * 16;
            int kl = half * 16;
            uint32_t ah[2][4];
#pragma unroll
            for (int t = 0; t < 2; t++) {
                int m0 = wm * 32 + t * 16;
                ldsm_x4t(ah[t], smb + A_SM +
                         (uint32_t)(((kg + a_k_off) * AKS + m0 + a_m_off) * 2));
            }
#pragma unroll
            for (int u = 0; u < 8; u++) {
                int n = wn * 64 + u * 8 + w_row;
                uint32_t bh[2];
                ldsm_x2(bh, smb + (uint32_t)(wbase + (n * WKS + kl + w_col_off) * 2));
#pragma unroll
                for (int t = 0; t < 2; t++)
                    mma16816(acc[t][u], ah[t], bh);
            }
        }
        if (s + 1 < 5) {
            if (s + 1 == 4) stWtail(sm, rwv, tid, (s + 1) & 1);
            else            stW256(sm, rwv, tid, (s + 1) & 1);
            if (s + 2 < 5) {
                if (s + 2 == 4) ldWtail(rwv, g_W1h, tid);
                else            ldW256(rwv, g_W1h, (s + 2) * 64, tid);
            }
        }
        __syncthreads();
    }

    // epilogue 1: bias + relu -> A [c][p] ; stage full W2 resident
#pragma unroll
    for (int t = 0; t < 2; t++) {
#pragma unroll
        for (int u = 0; u < 8; u++) {
            int r  = wm * 32 + t * 16 + qrow;
            int cc = wn * 64 + u * 8 + qk;
            float bb0 = __ldg(&b1[cc]), bb1 = __ldg(&b1[cc + 1]);
            float v0 = fmaxf(acc[t][u][0] + bb0, 0.f);
            float v1 = fmaxf(acc[t][u][1] + bb1, 0.f);
            float v2 = fmaxf(acc[t][u][2] + bb0, 0.f);
            float v3 = fmaxf(acc[t][u][3] + bb1, 0.f);
            *(__half*)(sm + A_SM + (cc * AKS + r) * 2)           = __float2half_rn(v0);
            *(__half*)(sm + A_SM + ((cc + 1) * AKS + r) * 2)     = __float2half_rn(v1);
            *(__half*)(sm + A_SM + (cc * AKS + r + 8) * 2)       = __float2half_rn(v2);
            *(__half*)(sm + A_SM + ((cc + 1) * AKS + r + 8) * 2) = __float2half_rn(v3);
            acc[t][u][0] = acc[t][u][1] = acc[t][u][2] = acc[t][u][3] = 0.f;
        }
    }
#pragma unroll
    for (int j = 0; j < 16; j++) {
        int idx = tid + j * 512;
        int row = idx >> 5, q = idx & 31;
        *(uint4*)(sm + W_SM + (row * WK2 + q * 8) * 2) =
            *(const uint4*)(g_W2h + row * 256 + q * 8);
    }
    __syncthreads();

    // ===== layer 2: barrier-free mainloop =====
#pragma unroll 4
    for (int kb = 0; kb < 16; kb++) {
        int kg = kb * 16;
        uint32_t ah[2][4];
#pragma unroll
        for (int t = 0; t < 2; t++) {
            int m0 = wm * 32 + t * 16;
            ldsm_x4t(ah[t], smb + A_SM +
                     (uint32_t)(((kg + a_k_off) * AKS + m0 + a_m_off) * 2));
        }
#pragma unroll
        for (int u = 0; u < 8; u++) {
            int n = wn * 64 + u * 8 + w_row;
            uint32_t bh[2];
            ldsm_x2(bh, smb + W_SM + (uint32_t)((n * WK2 + kg + w_col_off) * 2));
#pragma unroll
            for (int t = 0; t < 2; t++)
                mma16816(acc[t][u], ah[t], bh);
        }
    }
    __syncthreads();

    // epilogue 2 -> A ; stage W3 (32x256, stride WK2)
#pragma unroll
    for (int t = 0; t < 2; t++) {
#pragma unroll
        for (int u = 0; u < 8; u++) {
            int r  = wm * 32 + t * 16 + qrow;
            int cc = wn * 64 + u * 8 + qk;
            float bb0 = __ldg(&b2[cc]), bb1 = __ldg(&b2[cc + 1]);
            float v0 = fmaxf(acc[t][u][0] + bb0, 0.f);
            float v1 = fmaxf(acc[t][u][1] + bb1, 0.f);
            float v2 = fmaxf(acc[t][u][2] + bb0, 0.f);
            float v3 = fmaxf(acc[t][u][3] + bb1, 0.f);
            *(__half*)(sm + A_SM + (cc * AKS + r) * 2)           = __float2half_rn(v0);
            *(__half*)(sm + A_SM + ((cc + 1) * AKS + r) * 2)     = __float2half_rn(v1);
            *(__half*)(sm + A_SM + (cc * AKS + r + 8) * 2)       = __float2half_rn(v2);
            *(__half*)(sm + A_SM + ((cc + 1) * AKS + r + 8) * 2) = __float2half_rn(v3);
            acc[t][u][0] = acc[t][u][1] = acc[t][u][2] = acc[t][u][3] = 0.f;
        }
    }
#pragma unroll
    for (int j = 0; j < 2; j++) {
        int idx = tid + j * 512;
        int row = idx >> 5, q = idx & 31;
        *(uint4*)(sm + W_SM + (row * WK2 + q * 8) * 2) =
            *(const uint4*)(g_W3h + row * 256 + q * 8);
    }
    __syncthreads();

    // ===== layer 3 (N=19 padded to 24, wn==0 computes) =====
    if (wn == 0) {
#pragma unroll 4
        for (int kb = 0; kb < 16; kb++) {
            int kg = kb * 16;
            uint32_t ah[2][4];
#pragma unroll
            for (int t = 0; t < 2; t++) {
                int m0 = wm * 32 + t * 16;
                ldsm_x4t(ah[t], smb + A_SM +
                         (uint32_t)(((kg + a_k_off) * AKS + m0 + a_m_off) * 2));
            }
#pragma unroll
            for (int u = 0; u < 3; u++) {
                int n = u * 8 + w_row;
                uint32_t bh[2];
                ldsm_x2(bh, smb + W_SM + (uint32_t)((n * WK2 + kg + w_col_off) * 2));
#pragma unroll
                for (int t = 0; t < 2; t++)
                    mma16816(acc[t][u], ah[t], bh);
            }
        }

#pragma unroll
        for (int t = 0; t < 2; t++) {
#pragma unroll
            for (int u = 0; u < 3; u++) {
                int cc = u * 8 + qk;
#pragma unroll
                for (int half = 0; half < 2; half++) {
                    int r = wm * 32 + t * 16 + qrow + half * 8;
                    int pix = sidx[r];
                    float v0 = acc[t][u][half * 2 + 0];
                    float v1 = acc[t][u][half * 2 + 1];
                    if (cc < NC)
                        out[((size_t)b * NC + cc) * HW + pix] = v0 + __ldg(&b3[cc]);
                    if (cc + 1 < NC)
                        out[((size_t)b * NC + cc + 1) * HW + pix] = v1 + __ldg(&b3[cc + 1]);
                }
            }
        }
    }
}

// ---------------- launch (single stream) ----------------
extern "C" void kernel_launch(void* const* d_in, const int* in_sizes, int n_in,
                              void* d_out, int out_size)
{
    (void)in_sizes; (void)n_in; (void)out_size;
    const float* coarse = (const float*)d_in[0];
    const float* fine   = (const float*)d_in[1];
    const float* w1 = (const float*)d_in[2];
    const float* b1 = (const float*)d_in[3];
    const float* w2 = (const float*)d_in[4];
    const float* b2 = (const float*)d_in[5];
    const float* w3 = (const float*)d_in[6];
    const float* b3 = (const float*)d_in[7];
    float* out = (float*)d_out;

    static float* unc = nullptr;
    static bool init_done = false;
    if (!init_done) {
        cudaGetSymbolAddress((void**)&unc, g_unc);
        cudaFuncSetAttribute(mlp_mma_kernel,
                             cudaFuncAttributeMaxDynamicSharedMemorySize, SM_TOTAL);
        init_done = true;
    }

    upsample_unc_kernel<<<B * HF, WF>>>(coarse, out, unc, w1, w2, w3);
    topk_kernel<<<B, 1024>>>();
    gather_kernel<<<B * 144, 256>>>(fine, out);
    mlp_mma_kernel<<<B * 16, 512, SM_TOTAL>>>(b1, b2, b3, out);
}